// round 1
// baseline (speedup 1.0000x reference)
#include <cuda_runtime.h>
#include <math.h>

#define BBATCH 256
#define LLEN   128
#define KNBR   6
#define FAD    39
#define FBD    10
#define DDIM   128
#define NRAD   3
#define NTS    2
#define NEGV   (-9e8f)

static const int M_ATOM = BBATCH * LLEN;          // 32768
static const int M_NBR  = BBATCH * LLEN * KNBR;   // 196608

// ---------------- scratch (device globals; no allocations) ----------------
__device__ float g_h   [32768 * 128];
__device__ float g_act [32768 * 128];
__device__ float g_ctx [32768 * 128];
__device__ float g_P   [32768 * 128];
__device__ float g_anbr[196608 * 49];
__device__ float g_nbr [196608 * 128];
__device__ float g_tn  [196608 * 128];
__device__ float g_gi  [32768 * 384];
__device__ float g_gh  [32768 * 384];
__device__ float g_sc  [32768];
__device__ float g_sn  [196608];
__device__ float g_molf[256 * 128];
__device__ float g_pred[256];

// ---------------- generic fp32 GEMM: C = act(A[M,Ka] @ W + bias) ----------
// TRANSW=false: W stored [Ka, N] row-major (C=A@W)
// TRANSW=true : W stored [N, Ka] row-major (C=A@W^T), used for GRU x@Wih.T
// act: 0=none, 1=leaky_relu(0.01)
template<bool TRANSW>
__global__ void gemm_k(const float* __restrict__ A, const float* __restrict__ W,
                       const float* __restrict__ bias, float* __restrict__ C,
                       int M, int Ka, int N, int act)
{
    const int BM = 64, BN = 128, BK = 16, TM = 8, TN = 4;
    __shared__ float As[BK][BM];
    __shared__ float Ws[BK][BN];
    const int tid  = threadIdx.x;            // 256 threads
    const int trow = tid >> 5;                // 0..7
    const int tcol = tid & 31;                // 0..31
    const int m0 = blockIdx.x * BM;
    const int n0 = blockIdx.y * BN;

    float acc[TM][TN];
#pragma unroll
    for (int i = 0; i < TM; ++i)
#pragma unroll
        for (int j = 0; j < TN; ++j) acc[i][j] = 0.f;

    const int nk = (Ka + BK - 1) / BK;
    for (int kt = 0; kt < nk; ++kt) {
        const int k0 = kt * BK;
        // load A tile (64x16), 4 elems/thread, k fastest
#pragma unroll
        for (int i = 0; i < 4; ++i) {
            int idx = tid + i * 256;
            int m = idx >> 4;
            int k = idx & 15;
            float v = 0.f;
            if (k0 + k < Ka) v = A[(size_t)(m0 + m) * Ka + k0 + k];
            As[k][m] = v;
        }
        // load W tile (16x128), 8 elems/thread
#pragma unroll
        for (int i = 0; i < 8; ++i) {
            int idx = tid + i * 256;
            int k = idx >> 7;
            int n = idx & 127;
            float v = 0.f;
            if (k0 + k < Ka) {
                if (TRANSW) v = W[(size_t)(n0 + n) * Ka + k0 + k];
                else        v = W[(size_t)(k0 + k) * N  + n0 + n];
            }
            Ws[k][n] = v;
        }
        __syncthreads();
#pragma unroll
        for (int k = 0; k < BK; ++k) {
            float a[TM], b[TN];
#pragma unroll
            for (int i = 0; i < TM; ++i) a[i] = As[k][trow * TM + i];
#pragma unroll
            for (int j = 0; j < TN; ++j) b[j] = Ws[k][tcol * TN + j];
#pragma unroll
            for (int i = 0; i < TM; ++i)
#pragma unroll
                for (int j = 0; j < TN; ++j)
                    acc[i][j] = fmaf(a[i], b[j], acc[i][j]);
        }
        __syncthreads();
    }
#pragma unroll
    for (int i = 0; i < TM; ++i) {
        int m = m0 + trow * TM + i;
#pragma unroll
        for (int j = 0; j < TN; ++j) {
            int n = n0 + tcol * TN + j;
            float v = acc[i][j] + bias[n];
            if (act == 1) v = v > 0.f ? v : 0.01f * v;
            C[(size_t)m * N + n] = v;
        }
    }
}

// ---------------- per-row dot with a D=128 vector ----------------
__global__ void dot128_k(const float* __restrict__ X, const float* __restrict__ v,
                         float* __restrict__ out)
{
    int row = blockIdx.x;
    int j = threadIdx.x;
    float p = X[(size_t)row * DDIM + j] * v[j];
#pragma unroll
    for (int o = 16; o > 0; o >>= 1) p += __shfl_down_sync(0xffffffffu, p, o);
    __shared__ float s[4];
    if ((j & 31) == 0) s[j >> 5] = p;
    __syncthreads();
    if (j == 0) out[row] = s[0] + s[1] + s[2] + s[3];
}

// ---------------- neighbor row assembly: concat(atom[aidx], bond[bidx]) ----
__global__ void assemble_nbr_k(const float* __restrict__ atom, const float* __restrict__ bond,
                               const int* __restrict__ adl, const int* __restrict__ bdl,
                               float* __restrict__ out)
{
    int r = blockIdx.x;                      // (b*L + l)*K + k
    int b = r / (LLEN * KNBR);
    int ai = adl[r];
    int bi = bdl[r];
    int t = threadIdx.x;                     // 64 threads
    if (t < FAD)
        out[(size_t)r * 49 + t] = atom[((size_t)b * LLEN + ai) * FAD + t];
    else if (t < 49)
        out[(size_t)r * 49 + t] = bond[((size_t)b * LLEN + bi) * FBD + (t - FAD)];
}

// ---------------- neighborhood attention (both d=0 and d>=1 modes) --------
// mode0=1: sn/TF indexed by (bl*K + k);  mode0=0: indexed by (b*L + adl[..])
__global__ void attn_k(const float* __restrict__ sc, const float* __restrict__ sn,
                       const float* __restrict__ TF, const int* __restrict__ adl,
                       const float* __restrict__ abp, float* __restrict__ ctx, int mode0)
{
    int bl = blockIdx.x;
    int b  = bl / LLEN;
    int j  = threadIdx.x;
    __shared__ float ws[KNBR];
    __shared__ int   rowidx[KNBR];
    if (j == 0) {
        float ab = abp[0];
        float s[KNBR], msk[KNBR];
        float mx = -1e30f;
#pragma unroll
        for (int k = 0; k < KNBR; ++k) {
            int id = adl[bl * KNBR + k];
            int src = mode0 ? (bl * KNBR + k) : (b * LLEN + id);
            rowidx[k] = src;
            float sco = sc[bl] + sn[src] + ab;
            sco = sco > 0.f ? sco : 0.01f * sco;
            bool pad = (id == LLEN - 1);
            if (pad) sco += NEGV;
            msk[k] = pad ? 0.f : 1.f;
            s[k] = sco;
            mx = fmaxf(mx, sco);
        }
        float sum = 0.f;
#pragma unroll
        for (int k = 0; k < KNBR; ++k) { s[k] = expf(s[k] - mx); sum += s[k]; }
#pragma unroll
        for (int k = 0; k < KNBR; ++k) ws[k] = s[k] / sum * msk[k];
    }
    __syncthreads();
    float c = 0.f;
#pragma unroll
    for (int k = 0; k < KNBR; ++k)
        c = fmaf(ws[k], TF[(size_t)rowidx[k] * DDIM + j], c);
    c = c > 0.f ? c : expm1f(c);             // elu
    ctx[(size_t)bl * DDIM + j] = c;
}

// ---------------- GRU gate fusion ----------------
__global__ void gru_gate_k(const float* __restrict__ gi, const float* __restrict__ gh,
                           float* __restrict__ h, float* __restrict__ act, int M)
{
    int idx = blockIdx.x * blockDim.x + threadIdx.x;
    if (idx >= M * DDIM) return;
    int m = idx >> 7, j = idx & 127;
    size_t base = (size_t)m * 384;
    float ir = gi[base + j], iz = gi[base + 128 + j], in = gi[base + 256 + j];
    float hr = gh[base + j], hz = gh[base + 128 + j], hn = gh[base + 256 + j];
    float r = 1.f / (1.f + expf(-(ir + hr)));
    float z = 1.f / (1.f + expf(-(iz + hz)));
    float n = tanhf(in + r * hn);
    float hv = h[idx];
    float hnew = (1.f - z) * n + z * hv;
    h[idx] = hnew;
    act[idx] = hnew > 0.f ? hnew : 0.f;
}

// ---------------- masked sum over atoms ----------------
__global__ void molsum_k(const float* __restrict__ act, const float* __restrict__ mask,
                         float* __restrict__ molf)
{
    int b = blockIdx.x, j = threadIdx.x;
    float s = 0.f;
    for (int l = 0; l < LLEN; ++l)
        s = fmaf(act[((size_t)b * LLEN + l) * DDIM + j], mask[b * LLEN + l], s);
    molf[b * DDIM + j] = s;
}

// ---------------- per-molecule mol-attention + GRU (T steps inside) -------
__device__ __forceinline__ float blk_sum(float v, float* red, int j)
{
#pragma unroll
    for (int o = 16; o > 0; o >>= 1) v += __shfl_down_sync(0xffffffffu, v, o);
    if ((j & 31) == 0) red[j >> 5] = v;
    __syncthreads();
    v = red[0] + red[1] + red[2] + red[3];
    __syncthreads();
    return v;
}
__device__ __forceinline__ float blk_max(float v, float* red, int j)
{
#pragma unroll
    for (int o = 16; o > 0; o >>= 1) v = fmaxf(v, __shfl_down_sync(0xffffffffu, v, o));
    if ((j & 31) == 0) red[j >> 5] = v;
    __syncthreads();
    v = fmaxf(fmaxf(red[0], red[1]), fmaxf(red[2], red[3]));
    __syncthreads();
    return v;
}

__global__ void mol_k(const float* __restrict__ molf_in, const float* __restrict__ mask,
                      const float* __restrict__ snm, const float* __restrict__ Pm,
                      const float* __restrict__ maw, const float* __restrict__ mab,
                      const float* __restrict__ wih, const float* __restrict__ whh,
                      const float* __restrict__ bih, const float* __restrict__ bhh,
                      const float* __restrict__ outw, const float* __restrict__ outb,
                      float* __restrict__ molf_out, float* __restrict__ pred)
{
    int b = blockIdx.x;
    int j = threadIdx.x;                     // 128: feature index AND atom index
    __shared__ float smolf[DDIM];
    __shared__ float w[LLEN];
    __shared__ float sctx[DDIM];
    __shared__ float red[4];
    smolf[j] = molf_in[b * DDIM + j];
    float mymask = mask[b * LLEN + j];
    float mysnm  = snm[b * LLEN + j];
    float mabv   = mab[0];

    for (int t = 0; t < NTS; ++t) {
        __syncthreads();
        float amj = fmaxf(smolf[j], 0.f);                 // relu(mol_feature)
        float scv = blk_sum(amj * maw[j], red, j);        // dot(act_mol, maw[0:D])
        float sco = scv + mysnm + mabv;
        sco = sco > 0.f ? sco : 0.01f * sco;
        if (mymask == 0.f) sco += NEGV;
        float mx = blk_max(sco, red, j);
        float ev = expf(sco - mx);
        float ss = blk_sum(ev, red, j);
        w[j] = ev / ss * mymask;
        __syncthreads();
        float c = 0.f;
#pragma unroll 4
        for (int l = 0; l < LLEN; ++l)
            c = fmaf(w[l], Pm[((size_t)b * LLEN + l) * DDIM + j], c);
        c = c > 0.f ? c : expm1f(c);
        sctx[j] = c;
        __syncthreads();
        // mol GRU: thread j computes gates for hidden unit j
        float gi0 = bih[j], gi1 = bih[DDIM + j], gi2 = bih[2 * DDIM + j];
        float gh0 = bhh[j], gh1 = bhh[DDIM + j], gh2 = bhh[2 * DDIM + j];
        const float* wi0 = wih + (size_t)j * DDIM;
        const float* wi1 = wih + (size_t)(DDIM + j) * DDIM;
        const float* wi2 = wih + (size_t)(2 * DDIM + j) * DDIM;
        const float* wh0 = whh + (size_t)j * DDIM;
        const float* wh1 = whh + (size_t)(DDIM + j) * DDIM;
        const float* wh2 = whh + (size_t)(2 * DDIM + j) * DDIM;
#pragma unroll 4
        for (int k = 0; k < DDIM; ++k) {
            float ck = sctx[k], hk = smolf[k];
            gi0 = fmaf(ck, wi0[k], gi0);
            gi1 = fmaf(ck, wi1[k], gi1);
            gi2 = fmaf(ck, wi2[k], gi2);
            gh0 = fmaf(hk, wh0[k], gh0);
            gh1 = fmaf(hk, wh1[k], gh1);
            gh2 = fmaf(hk, wh2[k], gh2);
        }
        float r = 1.f / (1.f + expf(-(gi0 + gh0)));
        float z = 1.f / (1.f + expf(-(gi1 + gh1)));
        float n = tanhf(gi2 + r * gh2);
        float hnew = (1.f - z) * n + z * smolf[j];
        __syncthreads();
        smolf[j] = hnew;
    }
    __syncthreads();
    molf_out[b * DDIM + j] = smolf[j];
    float tot = blk_sum(smolf[j] * outw[j], red, j);
    if (j == 0) pred[b] = tot + outb[0];
}

__global__ void copy_k(const float* __restrict__ src, float* __restrict__ dst, int n)
{
    int i = blockIdx.x * blockDim.x + threadIdx.x;
    if (i < n) dst[i] = src[i];
}

// ---------------- launcher ----------------
extern "C" void kernel_launch(void* const* d_in, const int* in_sizes, int n_in,
                              void* d_out, int out_size)
{
    const float* atom_list    = (const float*)d_in[0];
    const float* bond_list    = (const float*)d_in[1];
    const float* atom_mask    = (const float*)d_in[2];
    const float* atom_fc_w    = (const float*)d_in[3];
    const float* atom_fc_b    = (const float*)d_in[4];
    const float* nbr_fc_w     = (const float*)d_in[5];
    const float* nbr_fc_b     = (const float*)d_in[6];
    const float* align_w      = (const float*)d_in[7];   // [R, 2D]
    const float* align_b      = (const float*)d_in[8];   // [R]
    const float* attend_w     = (const float*)d_in[9];   // [R, D, D]
    const float* attend_b     = (const float*)d_in[10];  // [R, D]
    const float* gru_wih      = (const float*)d_in[11];  // [R, 3D, D]
    const float* gru_whh      = (const float*)d_in[12];
    const float* gru_bih      = (const float*)d_in[13];  // [R, 3D]
    const float* gru_bhh      = (const float*)d_in[14];
    const float* mol_align_w  = (const float*)d_in[15];  // [2D]
    const float* mol_align_b  = (const float*)d_in[16];  // [1]
    const float* mol_attend_w = (const float*)d_in[17];  // [D, D]
    const float* mol_attend_b = (const float*)d_in[18];  // [D]
    const float* mol_gru_wih  = (const float*)d_in[19];  // [3D, D]
    const float* mol_gru_whh  = (const float*)d_in[20];
    const float* mol_gru_bih  = (const float*)d_in[21];
    const float* mol_gru_bhh  = (const float*)d_in[22];
    const float* out_w        = (const float*)d_in[23];  // [D]
    const float* out_b        = (const float*)d_in[24];  // [1]
    const int*   adl          = (const int*)d_in[25];    // [B, L, K]
    const int*   bdl          = (const int*)d_in[26];

    float *p_h, *p_act, *p_ctx, *p_P, *p_anbr, *p_nbr, *p_tn, *p_gi, *p_gh,
          *p_sc, *p_sn, *p_molf, *p_pred;
    cudaGetSymbolAddress((void**)&p_h,    g_h);
    cudaGetSymbolAddress((void**)&p_act,  g_act);
    cudaGetSymbolAddress((void**)&p_ctx,  g_ctx);
    cudaGetSymbolAddress((void**)&p_P,    g_P);
    cudaGetSymbolAddress((void**)&p_anbr, g_anbr);
    cudaGetSymbolAddress((void**)&p_nbr,  g_nbr);
    cudaGetSymbolAddress((void**)&p_tn,   g_tn);
    cudaGetSymbolAddress((void**)&p_gi,   g_gi);
    cudaGetSymbolAddress((void**)&p_gh,   g_gh);
    cudaGetSymbolAddress((void**)&p_sc,   g_sc);
    cudaGetSymbolAddress((void**)&p_sn,   g_sn);
    cudaGetSymbolAddress((void**)&p_molf, g_molf);
    cudaGetSymbolAddress((void**)&p_pred, g_pred);

    float* out = (float*)d_out;
    const int gA = M_ATOM / 64;   // 512
    const int gN = M_NBR / 64;    // 3072

    // atom_feature = lrelu(atom_list @ Wfc + b)  -> h
    gemm_k<false><<<dim3(gA, 1), 256>>>(atom_list, atom_fc_w, atom_fc_b, p_h, M_ATOM, FAD, DDIM, 1);
    // neighbor rows assembled + fc
    assemble_nbr_k<<<M_NBR, 64>>>(atom_list, bond_list, adl, bdl, p_anbr);
    gemm_k<false><<<dim3(gN, 1), 256>>>(p_anbr, nbr_fc_w, nbr_fc_b, p_nbr, M_NBR, 49, DDIM, 1);

    // ---- radius 0 ----
    dot128_k<<<M_ATOM, 128>>>(p_h,   align_w,          p_sc);   // dot(cur, aw[:D])
    dot128_k<<<M_NBR,  128>>>(p_nbr, align_w + DDIM,   p_sn);   // dot(nbr, aw[D:])
    gemm_k<false><<<dim3(gN, 1), 256>>>(p_nbr, attend_w, attend_b, p_tn, M_NBR, DDIM, DDIM, 0);
    attn_k<<<M_ATOM, 128>>>(p_sc, p_sn, p_tn, adl, align_b, p_ctx, 1);
    gemm_k<true><<<dim3(gA, 3), 256>>>(p_ctx, gru_wih, gru_bih, p_gi, M_ATOM, DDIM, 384, 0);
    gemm_k<true><<<dim3(gA, 3), 256>>>(p_h,   gru_whh, gru_bhh, p_gh, M_ATOM, DDIM, 384, 0);
    gru_gate_k<<<(M_ATOM * DDIM + 255) / 256, 256>>>(p_gi, p_gh, p_h, p_act, M_ATOM);

    // ---- radii 1..R-1 (transform factored through the gather) ----
    for (int d = 1; d < NRAD; ++d) {
        dot128_k<<<M_ATOM, 128>>>(p_act, align_w + d * 2 * DDIM,        p_sc);
        dot128_k<<<M_ATOM, 128>>>(p_act, align_w + d * 2 * DDIM + DDIM, p_sn);
        gemm_k<false><<<dim3(gA, 1), 256>>>(p_act, attend_w + (size_t)d * DDIM * DDIM,
                                            attend_b + d * DDIM, p_P, M_ATOM, DDIM, DDIM, 0);
        attn_k<<<M_ATOM, 128>>>(p_sc, p_sn, p_P, adl, align_b + d, p_ctx, 0);
        gemm_k<true><<<dim3(gA, 3), 256>>>(p_ctx, gru_wih + (size_t)d * 384 * DDIM,
                                           gru_bih + d * 384, p_gi, M_ATOM, DDIM, 384, 0);
        gemm_k<true><<<dim3(gA, 3), 256>>>(p_h, gru_whh + (size_t)d * 384 * DDIM,
                                           gru_bhh + d * 384, p_gh, M_ATOM, DDIM, 384, 0);
        gru_gate_k<<<(M_ATOM * DDIM + 255) / 256, 256>>>(p_gi, p_gh, p_h, p_act, M_ATOM);
    }

    // ---- molecule phase ----
    molsum_k<<<BBATCH, 128>>>(p_act, atom_mask, p_molf);
    gemm_k<false><<<dim3(gA, 1), 256>>>(p_act, mol_attend_w, mol_attend_b, p_P, M_ATOM, DDIM, DDIM, 0);
    dot128_k<<<M_ATOM, 128>>>(p_act, mol_align_w + DDIM, p_sn);
    mol_k<<<BBATCH, 128>>>(p_molf, atom_mask, p_sn, p_P, mol_align_w, mol_align_b,
                           mol_gru_wih, mol_gru_whh, mol_gru_bih, mol_gru_bhh,
                           out_w, out_b, p_molf, p_pred);

    // ---- outputs: (h, mol_prediction) flattened ----
    const int HN = M_ATOM * DDIM;
    if (out_size >= HN + BBATCH) {
        copy_k<<<(HN + 255) / 256, 256>>>(p_h, out, HN);
        copy_k<<<1, 256>>>(p_pred, out + HN, BBATCH);
    } else if (out_size == BBATCH) {
        copy_k<<<1, 256>>>(p_pred, out, BBATCH);
    } else {
        int n = out_size < HN ? out_size : HN;
        copy_k<<<(n + 255) / 256, 256>>>(p_h, out, n);
    }
    (void)in_sizes; (void)n_in;
}

// round 4
// speedup vs baseline: 1.5992x; 1.5992x over previous
#include <cuda_runtime.h>
#include <mma.h>
#include <math.h>

using namespace nvcuda;

#define BBATCH 256
#define LLEN   128
#define KNBR   6
#define FAD    39
#define FBD    10
#define DDIM   128
#define NRAD   3
#define NTS    2
#define NEGV   (-9e8f)

static const int M_ATOM = BBATCH * LLEN;          // 32768

// ---------------- scratch (device globals; no allocations) ----------------
__device__ __align__(256) float g_h    [32768 * 128];
__device__ __align__(256) float g_act  [32768 * 128];
__device__ __align__(256) float g_ctx  [32768 * 128];
__device__ __align__(256) float g_P    [32768 * 128];
__device__ __align__(256) float g_atomT[32768 * 128];
__device__ __align__(256) float g_bondT[32768 * 128];
__device__ __align__(256) float g_A64  [32768 * 64];
__device__ __align__(256) float g_B32  [32768 * 32];
__device__ __align__(256) float g_gi   [32768 * 384];
__device__ __align__(256) float g_gh   [32768 * 384];
__device__ __align__(256) float g_sc   [32768];
__device__ __align__(256) float g_sn   [32768];
__device__ __align__(256) float g_sumw [32768];
__device__ __align__(256) float g_Wa   [64 * 128];
__device__ __align__(256) float g_Wt   [64 * 128];
__device__ __align__(256) float g_Wb   [32 * 128];
__device__ __align__(256) float g_molf [256 * 128];
__device__ __align__(256) float g_pred [256];

// ---------------- 3xTF32 split helper ----------------
template<typename FragT>
__device__ __forceinline__ void split3(FragT& hi, FragT& lo)
{
#pragma unroll
    for (int e = 0; e < hi.num_elements; ++e) {
        float x = hi.x[e];
        float h = wmma::__float_to_tf32(x);
        hi.x[e] = h;
        lo.x[e] = wmma::__float_to_tf32(x - h);
    }
}

// =================== split-tf32 tensor-core GEMM (fp32-accurate) ===========
// C[M,N] = epilogue(A[M,K] @ B)
// BL=0: W stored [K,N] row-major.  BL=1: W stored [N,K] row-major (B = W^T).
// MODE: 0 raw, 1 lrelu(x+bias[n]), 3 elu(x + rowscale[m]*bias[n])
// Requires: M%128==0, grid.y=N/64, K%32==0, 16B-aligned pointers.
template<int BL, int MODE>
__global__ void __launch_bounds__(256) gemm_tf32_k(
    const float* __restrict__ A, const float* __restrict__ W,
    const float* __restrict__ bias, const float* __restrict__ rowscale,
    float* __restrict__ C, int M, int K, int N)
{
    constexpr int BM = 128, BN = 64, BK = 32;
    __shared__ float buf[128 * 72];                 // As(128x36) + Bs, reused as Cs(128x72)
    float* As = buf;                                 // ld 36
    float* Bs = buf + 128 * 36;                      // row: 32x68 ; col: 64x36
    const int tid  = threadIdx.x;
    const int warp = tid >> 5;
    const int wm = warp >> 1, wn = warp & 1;         // 4 x 2 warp grid, each 32x32
    const int m0 = blockIdx.x * BM, n0 = blockIdx.y * BN;

    wmma::fragment<wmma::accumulator, 16, 16, 8, float> acc[2][2];
#pragma unroll
    for (int mi = 0; mi < 2; ++mi)
#pragma unroll
        for (int ni = 0; ni < 2; ++ni) wmma::fill_fragment(acc[mi][ni], 0.f);

    for (int k0 = 0; k0 < K; k0 += BK) {
        // A tile: 128 x 32, float4
#pragma unroll
        for (int t = 0; t < 4; ++t) {
            int i = tid + t * 256;
            int row = i >> 3, c4 = i & 7;
            float4 v = *(const float4*)(A + (size_t)(m0 + row) * K + k0 + c4 * 4);
            *(float4*)(As + row * 36 + c4 * 4) = v;
        }
        // B tile
#pragma unroll
        for (int t = 0; t < 2; ++t) {
            int i = tid + t * 256;
            if (BL == 0) {
                int k = i >> 4, c4 = i & 15;
                float4 v = *(const float4*)(W + (size_t)(k0 + k) * N + n0 + c4 * 4);
                *(float4*)(Bs + k * 68 + c4 * 4) = v;
            } else {
                int n = i >> 3, c4 = i & 7;
                float4 v = *(const float4*)(W + (size_t)(n0 + n) * K + k0 + c4 * 4);
                *(float4*)(Bs + n * 36 + c4 * 4) = v;
            }
        }
        __syncthreads();
#pragma unroll
        for (int kc = 0; kc < BK; kc += 8) {
            wmma::fragment<wmma::matrix_a, 16, 16, 8, wmma::precision::tf32, wmma::row_major> ah[2], al[2];
#pragma unroll
            for (int mi = 0; mi < 2; ++mi) {
                wmma::load_matrix_sync(ah[mi], As + (wm * 32 + mi * 16) * 36 + kc, 36);
                split3(ah[mi], al[mi]);
            }
            if (BL == 0) {
                wmma::fragment<wmma::matrix_b, 16, 16, 8, wmma::precision::tf32, wmma::row_major> bh[2], bl[2];
#pragma unroll
                for (int ni = 0; ni < 2; ++ni) {
                    wmma::load_matrix_sync(bh[ni], Bs + kc * 68 + wn * 32 + ni * 16, 68);
                    split3(bh[ni], bl[ni]);
                }
#pragma unroll
                for (int mi = 0; mi < 2; ++mi)
#pragma unroll
                    for (int ni = 0; ni < 2; ++ni) {
                        wmma::mma_sync(acc[mi][ni], al[mi], bh[ni], acc[mi][ni]);
                        wmma::mma_sync(acc[mi][ni], ah[mi], bl[ni], acc[mi][ni]);
                        wmma::mma_sync(acc[mi][ni], ah[mi], bh[ni], acc[mi][ni]);
                    }
            } else {
                wmma::fragment<wmma::matrix_b, 16, 16, 8, wmma::precision::tf32, wmma::col_major> bh[2], bl[2];
#pragma unroll
                for (int ni = 0; ni < 2; ++ni) {
                    wmma::load_matrix_sync(bh[ni], Bs + (wn * 32 + ni * 16) * 36 + kc, 36);
                    split3(bh[ni], bl[ni]);
                }
#pragma unroll
                for (int mi = 0; mi < 2; ++mi)
#pragma unroll
                    for (int ni = 0; ni < 2; ++ni) {
                        wmma::mma_sync(acc[mi][ni], al[mi], bh[ni], acc[mi][ni]);
                        wmma::mma_sync(acc[mi][ni], ah[mi], bl[ni], acc[mi][ni]);
                        wmma::mma_sync(acc[mi][ni], ah[mi], bh[ni], acc[mi][ni]);
                    }
            }
        }
        __syncthreads();
    }
    // epilogue via smem staging
    float* Cs = buf;                                 // ld 72
#pragma unroll
    for (int mi = 0; mi < 2; ++mi)
#pragma unroll
        for (int ni = 0; ni < 2; ++ni)
            wmma::store_matrix_sync(Cs + (wm * 32 + mi * 16) * 72 + (wn * 32 + ni * 16),
                                    acc[mi][ni], 72, wmma::mem_row_major);
    __syncthreads();
#pragma unroll
    for (int t = 0; t < 8; ++t) {
        int i = tid + t * 256;
        int row = i >> 4, c4 = i & 15;
        float4 v = *(float4*)(Cs + row * 72 + c4 * 4);
        int n = n0 + c4 * 4;
        if (MODE == 1) {
            v.x += bias[n];     v.y += bias[n + 1];  v.z += bias[n + 2];  v.w += bias[n + 3];
            v.x = v.x > 0.f ? v.x : 0.01f * v.x;
            v.y = v.y > 0.f ? v.y : 0.01f * v.y;
            v.z = v.z > 0.f ? v.z : 0.01f * v.z;
            v.w = v.w > 0.f ? v.w : 0.01f * v.w;
        } else if (MODE == 3) {
            float rs = rowscale[m0 + row];
            v.x += rs * bias[n];     v.y += rs * bias[n + 1];
            v.z += rs * bias[n + 2]; v.w += rs * bias[n + 3];
            v.x = v.x > 0.f ? v.x : expm1f(v.x);
            v.y = v.y > 0.f ? v.y : expm1f(v.y);
            v.z = v.z > 0.f ? v.z : expm1f(v.z);
            v.w = v.w > 0.f ? v.w : expm1f(v.w);
        }
        *(float4*)(C + (size_t)(m0 + row) * N + n) = v;
    }
}

// ---------------- block reductions ----------------
__device__ __forceinline__ float blk_sum(float v, float* red, int j)
{
#pragma unroll
    for (int o = 16; o > 0; o >>= 1) v += __shfl_down_sync(0xffffffffu, v, o);
    if ((j & 31) == 0) red[j >> 5] = v;
    __syncthreads();
    v = red[0] + red[1] + red[2] + red[3];
    __syncthreads();
    return v;
}
__device__ __forceinline__ float blk_max(float v, float* red, int j)
{
#pragma unroll
    for (int o = 16; o > 0; o >>= 1) v = fmaxf(v, __shfl_down_sync(0xffffffffu, v, o));
    if ((j & 31) == 0) red[j >> 5] = v;
    __syncthreads();
    v = fmaxf(fmaxf(red[0], red[1]), fmaxf(red[2], red[3]));
    __syncthreads();
    return v;
}

// ---------------- padding kernels ----------------
__global__ void pad_atom_k(const float* __restrict__ atom, float* __restrict__ out)
{
    int r = blockIdx.x, t = threadIdx.x;             // 64 threads
    out[(size_t)r * 64 + t] = (t < FAD) ? atom[(size_t)r * FAD + t] : 0.f;
}
__global__ void pad_bond_k(const float* __restrict__ bond, float* __restrict__ out)
{
    int r = blockIdx.x, t = threadIdx.x;             // 32 threads
    out[(size_t)r * 32 + t] = (t < FBD) ? bond[(size_t)r * FBD + t] : 0.f;
}
// out rows [0,grid) of width 128; copies w rows [off, off+Ksrc), zero-pads rest
__global__ void pad_w_k(const float* __restrict__ w, float* __restrict__ out,
                        int Ksrc, int off)
{
    int r = blockIdx.x, j = threadIdx.x;
    out[r * 128 + j] = (r < Ksrc) ? w[(off + r) * 128 + j] : 0.f;
}

// ---------------- fused d=0 attention (neighbor features built on the fly) -
// v_k = lrelu(atomT[b,adl_k] + bondT[b,bdl_k] + nbias); scores, softmax,
// weighted sum of v_k (pre-transform) + sum of weights.
__global__ void attn0_k(const float* __restrict__ h, const float* __restrict__ atomT,
                        const float* __restrict__ bondT, const int* __restrict__ adl,
                        const int* __restrict__ bdl, const float* __restrict__ nbias,
                        const float* __restrict__ aw, const float* __restrict__ ab,
                        float* __restrict__ wnbr, float* __restrict__ sumw)
{
    int bl = blockIdx.x, j = threadIdx.x;            // 128 threads
    int bbase = (bl >> 7) << 7;                      // b * LLEN
    __shared__ float red[4];
    const int base = bl * KNBR;
    float sc = blk_sum(h[(size_t)bl * DDIM + j] * aw[j], red, j);
    float aw2 = aw[DDIM + j];
    float ab0 = ab[0];
    float nb  = nbias[j];
    float v[KNBR], s[KNBR], msk[KNBR];
#pragma unroll
    for (int k = 0; k < KNBR; ++k) {
        int ai = adl[base + k], bi = bdl[base + k];
        float x = atomT[(size_t)(bbase + ai) * DDIM + j]
                + bondT[(size_t)(bbase + bi) * DDIM + j] + nb;
        v[k] = x > 0.f ? x : 0.01f * x;
        msk[k] = (ai == LLEN - 1) ? 0.f : 1.f;
    }
#pragma unroll
    for (int k = 0; k < KNBR; ++k) {
        float d = blk_sum(v[k] * aw2, red, j);
        float sco = sc + d + ab0;
        sco = sco > 0.f ? sco : 0.01f * sco;
        if (msk[k] == 0.f) sco += NEGV;
        s[k] = sco;
    }
    float mx = -1e30f;
#pragma unroll
    for (int k = 0; k < KNBR; ++k) mx = fmaxf(mx, s[k]);
    float ss = 0.f;
#pragma unroll
    for (int k = 0; k < KNBR; ++k) { s[k] = expf(s[k] - mx); ss += s[k]; }
    float acc = 0.f, sw = 0.f;
#pragma unroll
    for (int k = 0; k < KNBR; ++k) {
        float w = s[k] / ss * msk[k];
        acc = fmaf(w, v[k], acc);
        sw += w;
    }
    wnbr[(size_t)bl * DDIM + j] = acc;
    if (j == 0) sumw[bl] = sw;
}

// ---------------- two dots in one pass over act ----------------
__global__ void dot2_k(const float* __restrict__ X, const float* __restrict__ w1,
                       const float* __restrict__ w2, float* __restrict__ o1,
                       float* __restrict__ o2)
{
    int row = blockIdx.x, j = threadIdx.x;
    __shared__ float red[4];
    float x = X[(size_t)row * DDIM + j];
    float a = blk_sum(x * w1[j], red, j);
    float b = blk_sum(x * w2[j], red, j);
    if (j == 0) { o1[row] = a; o2[row] = b; }
}
__global__ void dot128_k(const float* __restrict__ X, const float* __restrict__ v,
                         float* __restrict__ out)
{
    int row = blockIdx.x, j = threadIdx.x;
    __shared__ float red[4];
    float p = blk_sum(X[(size_t)row * DDIM + j] * v[j], red, j);
    if (j == 0) out[row] = p;
}

// ---------------- d>=1 attention (P raw: bias folded via sumw) -------------
__global__ void attn_k(const float* __restrict__ sc, const float* __restrict__ sn,
                       const float* __restrict__ P, const int* __restrict__ adl,
                       const float* __restrict__ abp, const float* __restrict__ tb,
                       float* __restrict__ ctx)
{
    int bl = blockIdx.x;
    int b  = bl >> 7;
    int j  = threadIdx.x;
    __shared__ float ws[KNBR];
    __shared__ float swsh;
    __shared__ int   rowidx[KNBR];
    if (j == 0) {
        float ab = abp[0];
        float s[KNBR], msk[KNBR];
        float mx = -1e30f;
#pragma unroll
        for (int k = 0; k < KNBR; ++k) {
            int id = adl[bl * KNBR + k];
            int src = b * LLEN + id;
            rowidx[k] = src;
            float sco = sc[bl] + sn[src] + ab;
            sco = sco > 0.f ? sco : 0.01f * sco;
            bool pad = (id == LLEN - 1);
            if (pad) sco += NEGV;
            msk[k] = pad ? 0.f : 1.f;
            s[k] = sco;
            mx = fmaxf(mx, sco);
        }
        float sum = 0.f;
#pragma unroll
        for (int k = 0; k < KNBR; ++k) { s[k] = expf(s[k] - mx); sum += s[k]; }
        float sw = 0.f;
#pragma unroll
        for (int k = 0; k < KNBR; ++k) { ws[k] = s[k] / sum * msk[k]; sw += ws[k]; }
        swsh = sw;
    }
    __syncthreads();
    float c = 0.f;
#pragma unroll
    for (int k = 0; k < KNBR; ++k)
        c = fmaf(ws[k], P[(size_t)rowidx[k] * DDIM + j], c);
    c += swsh * tb[j];
    c = c > 0.f ? c : expm1f(c);
    ctx[(size_t)bl * DDIM + j] = c;
}

// ---------------- GRU gate fusion (biases added here) ----------------
__global__ void gru_gate_k(const float* __restrict__ gi, const float* __restrict__ gh,
                           const float* __restrict__ bih, const float* __restrict__ bhh,
                           float* __restrict__ h, float* __restrict__ act, int M)
{
    int idx = blockIdx.x * blockDim.x + threadIdx.x;
    if (idx >= M * DDIM) return;
    int m = idx >> 7, j = idx & 127;
    size_t base = (size_t)m * 384;
    float ir = gi[base + j] + bih[j];
    float iz = gi[base + 128 + j] + bih[128 + j];
    float in = gi[base + 256 + j] + bih[256 + j];
    float hr = gh[base + j] + bhh[j];
    float hz = gh[base + 128 + j] + bhh[128 + j];
    float hn = gh[base + 256 + j] + bhh[256 + j];
    float r = 1.f / (1.f + expf(-(ir + hr)));
    float z = 1.f / (1.f + expf(-(iz + hz)));
    float n = tanhf(in + r * hn);
    float hv = h[idx];
    float hnew = (1.f - z) * n + z * hv;
    h[idx] = hnew;
    act[idx] = hnew > 0.f ? hnew : 0.f;
}

// ---------------- masked sum over atoms ----------------
__global__ void molsum_k(const float* __restrict__ act, const float* __restrict__ mask,
                         float* __restrict__ molf)
{
    int b = blockIdx.x, j = threadIdx.x;
    float s = 0.f;
    for (int l = 0; l < LLEN; ++l)
        s = fmaf(act[((size_t)b * LLEN + l) * DDIM + j], mask[b * LLEN + l], s);
    molf[b * DDIM + j] = s;
}

// ---------------- per-molecule mol-attention + GRU (T steps) ---------------
__global__ void mol_k(const float* __restrict__ molf_in, const float* __restrict__ mask,
                      const float* __restrict__ snm, const float* __restrict__ Pm,
                      const float* __restrict__ maw, const float* __restrict__ mab,
                      const float* __restrict__ matt_b,
                      const float* __restrict__ wih, const float* __restrict__ whh,
                      const float* __restrict__ bih, const float* __restrict__ bhh,
                      const float* __restrict__ outw, const float* __restrict__ outb,
                      float* __restrict__ molf_out, float* __restrict__ pred)
{
    int b = blockIdx.x;
    int j = threadIdx.x;                     // 128: feature index AND atom index
    __shared__ float smolf[DDIM];
    __shared__ float w[LLEN];
    __shared__ float sctx[DDIM];
    __shared__ float red[4];
    smolf[j] = molf_in[b * DDIM + j];
    float mymask = mask[b * LLEN + j];
    float mysnm  = snm[b * LLEN + j];
    float mabv   = mab[0];
    float mybias = matt_b[j];

    for (int t = 0; t < NTS; ++t) {
        __syncthreads();
        float amj = fmaxf(smolf[j], 0.f);
        float scv = blk_sum(amj * maw[j], red, j);
        float sco = scv + mysnm + mabv;
        sco = sco > 0.f ? sco : 0.01f * sco;
        if (mymask == 0.f) sco += NEGV;
        float mx = blk_max(sco, red, j);
        float ev = expf(sco - mx);
        float ss = blk_sum(ev, red, j);
        float wj = ev / ss * mymask;
        w[j] = wj;
        float sumw = blk_sum(wj, red, j);
        __syncthreads();
        float c = 0.f;
#pragma unroll 4
        for (int l = 0; l < LLEN; ++l)
            c = fmaf(w[l], Pm[((size_t)b * LLEN + l) * DDIM + j], c);
        c += sumw * mybias;
        c = c > 0.f ? c : expm1f(c);
        sctx[j] = c;
        __syncthreads();
        float gi0 = bih[j], gi1 = bih[DDIM + j], gi2 = bih[2 * DDIM + j];
        float gh0 = bhh[j], gh1 = bhh[DDIM + j], gh2 = bhh[2 * DDIM + j];
        const float* wi0 = wih + (size_t)j * DDIM;
        const float* wi1 = wih + (size_t)(DDIM + j) * DDIM;
        const float* wi2 = wih + (size_t)(2 * DDIM + j) * DDIM;
        const float* wh0 = whh + (size_t)j * DDIM;
        const float* wh1 = whh + (size_t)(DDIM + j) * DDIM;
        const float* wh2 = whh + (size_t)(2 * DDIM + j) * DDIM;
#pragma unroll 4
        for (int k = 0; k < DDIM; ++k) {
            float ck = sctx[k], hk = smolf[k];
            gi0 = fmaf(ck, wi0[k], gi0);
            gi1 = fmaf(ck, wi1[k], gi1);
            gi2 = fmaf(ck, wi2[k], gi2);
            gh0 = fmaf(hk, wh0[k], gh0);
            gh1 = fmaf(hk, wh1[k], gh1);
            gh2 = fmaf(hk, wh2[k], gh2);
        }
        float r = 1.f / (1.f + expf(-(gi0 + gh0)));
        float z = 1.f / (1.f + expf(-(gi1 + gh1)));
        float n = tanhf(gi2 + r * gh2);
        float hnew = (1.f - z) * n + z * smolf[j];
        __syncthreads();
        smolf[j] = hnew;
    }
    __syncthreads();
    molf_out[b * DDIM + j] = smolf[j];
    float tot = blk_sum(smolf[j] * outw[j], red, j);
    if (j == 0) pred[b] = tot + outb[0];
}

__global__ void copy_k(const float* __restrict__ src, float* __restrict__ dst, int n)
{
    int i = blockIdx.x * blockDim.x + threadIdx.x;
    if (i < n) dst[i] = src[i];
}

// ---------------- launcher ----------------
extern "C" void kernel_launch(void* const* d_in, const int* in_sizes, int n_in,
                              void* d_out, int out_size)
{
    const float* atom_list    = (const float*)d_in[0];
    const float* bond_list    = (const float*)d_in[1];
    const float* atom_mask    = (const float*)d_in[2];
    const float* atom_fc_w    = (const float*)d_in[3];
    const float* atom_fc_b    = (const float*)d_in[4];
    const float* nbr_fc_w     = (const float*)d_in[5];
    const float* nbr_fc_b     = (const float*)d_in[6];
    const float* align_w      = (const float*)d_in[7];   // [R, 2D]
    const float* align_b      = (const float*)d_in[8];   // [R]
    const float* attend_w     = (const float*)d_in[9];   // [R, D, D]
    const float* attend_b     = (const float*)d_in[10];  // [R, D]
    const float* gru_wih      = (const float*)d_in[11];  // [R, 3D, D]
    const float* gru_whh      = (const float*)d_in[12];
    const float* gru_bih      = (const float*)d_in[13];  // [R, 3D]
    const float* gru_bhh      = (const float*)d_in[14];
    const float* mol_align_w  = (const float*)d_in[15];  // [2D]
    const float* mol_align_b  = (const float*)d_in[16];  // [1]
    const float* mol_attend_w = (const float*)d_in[17];  // [D, D]
    const float* mol_attend_b = (const float*)d_in[18];  // [D]
    const float* mol_gru_wih  = (const float*)d_in[19];  // [3D, D]
    const float* mol_gru_whh  = (const float*)d_in[20];
    const float* mol_gru_bih  = (const float*)d_in[21];
    const float* mol_gru_bhh  = (const float*)d_in[22];
    const float* out_w        = (const float*)d_in[23];  // [D]
    const float* out_b        = (const float*)d_in[24];  // [1]
    const int*   adl          = (const int*)d_in[25];    // [B, L, K]
    const int*   bdl          = (const int*)d_in[26];

    float *p_h, *p_act, *p_ctx, *p_P, *p_atomT, *p_bondT, *p_A64, *p_B32,
          *p_gi, *p_gh, *p_sc, *p_sn, *p_sumw, *p_Wa, *p_Wt, *p_Wb,
          *p_molf, *p_pred;
    cudaGetSymbolAddress((void**)&p_h,     g_h);
    cudaGetSymbolAddress((void**)&p_act,   g_act);
    cudaGetSymbolAddress((void**)&p_ctx,   g_ctx);
    cudaGetSymbolAddress((void**)&p_P,     g_P);
    cudaGetSymbolAddress((void**)&p_atomT, g_atomT);
    cudaGetSymbolAddress((void**)&p_bondT, g_bondT);
    cudaGetSymbolAddress((void**)&p_A64,   g_A64);
    cudaGetSymbolAddress((void**)&p_B32,   g_B32);
    cudaGetSymbolAddress((void**)&p_gi,    g_gi);
    cudaGetSymbolAddress((void**)&p_gh,    g_gh);
    cudaGetSymbolAddress((void**)&p_sc,    g_sc);
    cudaGetSymbolAddress((void**)&p_sn,    g_sn);
    cudaGetSymbolAddress((void**)&p_sumw,  g_sumw);
    cudaGetSymbolAddress((void**)&p_Wa,    g_Wa);
    cudaGetSymbolAddress((void**)&p_Wt,    g_Wt);
    cudaGetSymbolAddress((void**)&p_Wb,    g_Wb);
    cudaGetSymbolAddress((void**)&p_molf,  g_molf);
    cudaGetSymbolAddress((void**)&p_pred,  g_pred);

    float* out = (float*)d_out;
    const int gA = M_ATOM / 128;  // 256

    // ---- pad inputs / weights ----
    pad_atom_k<<<M_ATOM, 64>>>(atom_list, p_A64);
    pad_bond_k<<<M_ATOM, 32>>>(bond_list, p_B32);
    pad_w_k<<<64, 128>>>(atom_fc_w, p_Wa, FAD, 0);        // atom fc weight
    pad_w_k<<<64, 128>>>(nbr_fc_w,  p_Wt, FAD, 0);        // nbr fc: atom part
    pad_w_k<<<32, 128>>>(nbr_fc_w,  p_Wb, FBD, FAD);      // nbr fc: bond part

    // atom_feature -> h ; factored nbr transforms (raw)
    gemm_tf32_k<0,1><<<dim3(gA, 2), 256>>>(p_A64, p_Wa, atom_fc_b, nullptr, p_h,     M_ATOM, 64, DDIM);
    gemm_tf32_k<0,0><<<dim3(gA, 2), 256>>>(p_A64, p_Wt, nullptr,   nullptr, p_atomT, M_ATOM, 64, DDIM);
    gemm_tf32_k<0,0><<<dim3(gA, 2), 256>>>(p_B32, p_Wb, nullptr,   nullptr, p_bondT, M_ATOM, 32, DDIM);

    // ---- radius 0: fused attention, then transform the weighted sum ----
    attn0_k<<<M_ATOM, 128>>>(p_h, p_atomT, p_bondT, adl, bdl, nbr_fc_b,
                             align_w, align_b, p_P, p_sumw);
    gemm_tf32_k<0,3><<<dim3(gA, 2), 256>>>(p_P, attend_w, attend_b, p_sumw, p_ctx, M_ATOM, DDIM, DDIM);
    gemm_tf32_k<1,0><<<dim3(gA, 6), 256>>>(p_ctx, gru_wih, nullptr, nullptr, p_gi, M_ATOM, DDIM, 384);
    gemm_tf32_k<1,0><<<dim3(gA, 6), 256>>>(p_h,   gru_whh, nullptr, nullptr, p_gh, M_ATOM, DDIM, 384);
    gru_gate_k<<<(M_ATOM * DDIM + 255) / 256, 256>>>(p_gi, p_gh, gru_bih, gru_bhh, p_h, p_act, M_ATOM);

    // ---- radii 1..R-1 ----
    for (int d = 1; d < NRAD; ++d) {
        dot2_k<<<M_ATOM, 128>>>(p_act, align_w + d * 2 * DDIM, align_w + d * 2 * DDIM + DDIM, p_sc, p_sn);
        gemm_tf32_k<0,0><<<dim3(gA, 2), 256>>>(p_act, attend_w + (size_t)d * DDIM * DDIM,
                                               nullptr, nullptr, p_P, M_ATOM, DDIM, DDIM);
        attn_k<<<M_ATOM, 128>>>(p_sc, p_sn, p_P, adl, align_b + d, attend_b + d * DDIM, p_ctx);
        gemm_tf32_k<1,0><<<dim3(gA, 6), 256>>>(p_ctx, gru_wih + (size_t)d * 384 * DDIM,
                                               nullptr, nullptr, p_gi, M_ATOM, DDIM, 384);
        gemm_tf32_k<1,0><<<dim3(gA, 6), 256>>>(p_h, gru_whh + (size_t)d * 384 * DDIM,
                                               nullptr, nullptr, p_gh, M_ATOM, DDIM, 384);
        gru_gate_k<<<(M_ATOM * DDIM + 255) / 256, 256>>>(p_gi, p_gh, gru_bih + d * 384,
                                                         gru_bhh + d * 384, p_h, p_act, M_ATOM);
    }

    // ---- molecule phase ----
    molsum_k<<<BBATCH, 128>>>(p_act, atom_mask, p_molf);
    gemm_tf32_k<0,0><<<dim3(gA, 2), 256>>>(p_act, mol_attend_w, nullptr, nullptr, p_P, M_ATOM, DDIM, DDIM);
    dot128_k<<<M_ATOM, 128>>>(p_act, mol_align_w + DDIM, p_sn);
    mol_k<<<BBATCH, 128>>>(p_molf, atom_mask, p_sn, p_P, mol_align_w, mol_align_b, mol_attend_b,
                           mol_gru_wih, mol_gru_whh, mol_gru_bih, mol_gru_bhh,
                           out_w, out_b, p_molf, p_pred);

    // ---- outputs: (h, mol_prediction) flattened ----
    const int HN = M_ATOM * DDIM;
    if (out_size >= HN + BBATCH) {
        copy_k<<<(HN + 255) / 256, 256>>>(p_h, out, HN);
        copy_k<<<1, 256>>>(p_pred, out + HN, BBATCH);
    } else if (out_size == BBATCH) {
        copy_k<<<1, 256>>>(p_pred, out, BBATCH);
    } else {
        int n = out_size < HN ? out_size : HN;
        copy_k<<<(n + 255) / 256, 256>>>(p_h, out, n);
    }
    (void)in_sizes; (void)n_in;
}

// round 5
// speedup vs baseline: 2.5795x; 1.6130x over previous
#include <cuda_runtime.h>
#include <cuda_bf16.h>
#include <mma.h>
#include <math.h>

using namespace nvcuda;

#define BBATCH 256
#define LLEN   128
#define KNBR   6
#define FAD    39
#define FBD    10
#define DDIM   128
#define NRAD   3
#define NTS    2
#define NEGV   (-9e8f)

static const int M_ATOM = BBATCH * LLEN;          // 32768

// ---------------- scratch (device globals; no allocations) ----------------
__device__ __align__(256) float g_h    [32768 * 128];
__device__ __align__(256) float g_act  [32768 * 128];
__device__ __align__(256) float g_ctx  [32768 * 128];
__device__ __align__(256) float g_P    [32768 * 128];
__device__ __align__(256) float g_atomT[32768 * 128];
__device__ __align__(256) float g_bondT[32768 * 128];
__device__ __align__(256) float g_A64  [32768 * 64];
__device__ __align__(256) float g_B32  [32768 * 32];
__device__ __align__(256) float g_gi   [32768 * 384];
__device__ __align__(256) float g_gh   [32768 * 384];
__device__ __align__(256) float g_sc   [32768];
__device__ __align__(256) float g_sn   [32768];
__device__ __align__(256) float g_sumw [32768];
__device__ __align__(256) float g_Wa   [64 * 128];
__device__ __align__(256) float g_Wt   [64 * 128];
__device__ __align__(256) float g_Wb   [32 * 128];
__device__ __align__(256) float g_molf [256 * 128];
__device__ __align__(256) float g_pred [256];

// ---------------- bf16 hi/lo split of two floats ----------------
__device__ __forceinline__ void f2bf_split2(float x, float y,
                                            __nv_bfloat162& hi, __nv_bfloat162& lo)
{
    __nv_bfloat16 hx = __float2bfloat16(x);
    __nv_bfloat16 hy = __float2bfloat16(y);
    hi = __nv_bfloat162(hx, hy);
    lo = __nv_bfloat162(__float2bfloat16(x - __bfloat162float(hx)),
                        __float2bfloat16(y - __bfloat162float(hy)));
}

// =================== bf16x3 split tensor-core GEMM (near-fp32) =============
// C[M,N] = epilogue(A[M,K] @ B)
// BL=0: W stored [K,N] row-major.  BL=1: W stored [N,K] row-major (B = W^T).
// MODE: 0 raw, 1 lrelu(x+bias[n]), 3 elu(x + rowscale[m]*bias[n])
// Requires: M%128==0, grid.y=N/64, K%32==0, 16B-aligned pointers.
template<int BL, int MODE>
__global__ void __launch_bounds__(256) gemm_bf16x3_k(
    const float* __restrict__ A, const float* __restrict__ W,
    const float* __restrict__ bias, const float* __restrict__ rowscale,
    float* __restrict__ C, int M, int K, int N)
{
    constexpr int BM = 128, BN = 64, BK = 32;
    constexpr int LDA = 40;                       // bf16 elements per A smem row
    constexpr int LDB = (BL == 0) ? 72 : 40;      // B smem leading dim
    __shared__ float buf[128 * 72];               // 36.9 KB; aliased below
    __nv_bfloat16* Ah = (__nv_bfloat16*)buf;                    // 128*40
    __nv_bfloat16* Al = Ah + 128 * LDA;                          // 128*40
    __nv_bfloat16* Bh = Al + 128 * LDA;
    __nv_bfloat16* Bl = Bh + ((BL == 0) ? 32 * 72 : 64 * 40);

    const int tid  = threadIdx.x;
    const int warp = tid >> 5;
    const int wm = warp >> 1, wn = warp & 1;      // 4 x 2 warp grid, each 32x32
    const int m0 = blockIdx.x * BM, n0 = blockIdx.y * BN;

    wmma::fragment<wmma::accumulator, 16, 16, 16, float> acc[2][2];
#pragma unroll
    for (int mi = 0; mi < 2; ++mi)
#pragma unroll
        for (int ni = 0; ni < 2; ++ni) wmma::fill_fragment(acc[mi][ni], 0.f);

    for (int k0 = 0; k0 < K; k0 += BK) {
        // A tile: 128 x 32 floats -> split bf16 hi/lo
#pragma unroll
        for (int t = 0; t < 4; ++t) {
            int i = tid + t * 256;                // [0,1024)
            int row = i >> 3, c4 = i & 7;         // col = c4*4
            float4 v = *(const float4*)(A + (size_t)(m0 + row) * K + k0 + c4 * 4);
            __nv_bfloat162 h0, l0, h1, l1;
            f2bf_split2(v.x, v.y, h0, l0);
            f2bf_split2(v.z, v.w, h1, l1);
            __nv_bfloat162* ph = (__nv_bfloat162*)(Ah + row * LDA + c4 * 4);
            __nv_bfloat162* pl = (__nv_bfloat162*)(Al + row * LDA + c4 * 4);
            ph[0] = h0; ph[1] = h1;
            pl[0] = l0; pl[1] = l1;
        }
        // B tile
#pragma unroll
        for (int t = 0; t < 2; ++t) {
            int i = tid + t * 256;                // [0,512)
            int r, c;
            const float* src;
            if (BL == 0) {                        // 32 x 64, row = k
                r = i >> 4; c = (i & 15) * 4;
                src = W + (size_t)(k0 + r) * N + n0 + c;
            } else {                              // 64 x 32, row = n
                r = i >> 3; c = (i & 7) * 4;
                src = W + (size_t)(n0 + r) * K + k0 + c;
            }
            float4 v = *(const float4*)src;
            __nv_bfloat162 h0, l0, h1, l1;
            f2bf_split2(v.x, v.y, h0, l0);
            f2bf_split2(v.z, v.w, h1, l1);
            __nv_bfloat162* ph = (__nv_bfloat162*)(Bh + r * LDB + c);
            __nv_bfloat162* pl = (__nv_bfloat162*)(Bl + r * LDB + c);
            ph[0] = h0; ph[1] = h1;
            pl[0] = l0; pl[1] = l1;
        }
        __syncthreads();
#pragma unroll
        for (int kc = 0; kc < BK; kc += 16) {
            wmma::fragment<wmma::matrix_a, 16, 16, 16, __nv_bfloat16, wmma::row_major> ah[2], al[2];
#pragma unroll
            for (int mi = 0; mi < 2; ++mi) {
                wmma::load_matrix_sync(ah[mi], Ah + (wm * 32 + mi * 16) * LDA + kc, LDA);
                wmma::load_matrix_sync(al[mi], Al + (wm * 32 + mi * 16) * LDA + kc, LDA);
            }
            if (BL == 0) {
                wmma::fragment<wmma::matrix_b, 16, 16, 16, __nv_bfloat16, wmma::row_major> bh[2], bl[2];
#pragma unroll
                for (int ni = 0; ni < 2; ++ni) {
                    wmma::load_matrix_sync(bh[ni], Bh + kc * LDB + wn * 32 + ni * 16, LDB);
                    wmma::load_matrix_sync(bl[ni], Bl + kc * LDB + wn * 32 + ni * 16, LDB);
                }
#pragma unroll
                for (int mi = 0; mi < 2; ++mi)
#pragma unroll
                    for (int ni = 0; ni < 2; ++ni) {
                        wmma::mma_sync(acc[mi][ni], ah[mi], bl[ni], acc[mi][ni]);
                        wmma::mma_sync(acc[mi][ni], al[mi], bh[ni], acc[mi][ni]);
                        wmma::mma_sync(acc[mi][ni], ah[mi], bh[ni], acc[mi][ni]);
                    }
            } else {
                wmma::fragment<wmma::matrix_b, 16, 16, 16, __nv_bfloat16, wmma::col_major> bh[2], bl[2];
#pragma unroll
                for (int ni = 0; ni < 2; ++ni) {
                    wmma::load_matrix_sync(bh[ni], Bh + (wn * 32 + ni * 16) * LDB + kc, LDB);
                    wmma::load_matrix_sync(bl[ni], Bl + (wn * 32 + ni * 16) * LDB + kc, LDB);
                }
#pragma unroll
                for (int mi = 0; mi < 2; ++mi)
#pragma unroll
                    for (int ni = 0; ni < 2; ++ni) {
                        wmma::mma_sync(acc[mi][ni], ah[mi], bl[ni], acc[mi][ni]);
                        wmma::mma_sync(acc[mi][ni], al[mi], bh[ni], acc[mi][ni]);
                        wmma::mma_sync(acc[mi][ni], ah[mi], bh[ni], acc[mi][ni]);
                    }
            }
        }
        __syncthreads();
    }
    // epilogue via smem staging
    float* Cs = buf;                               // ld 72
#pragma unroll
    for (int mi = 0; mi < 2; ++mi)
#pragma unroll
        for (int ni = 0; ni < 2; ++ni)
            wmma::store_matrix_sync(Cs + (wm * 32 + mi * 16) * 72 + (wn * 32 + ni * 16),
                                    acc[mi][ni], 72, wmma::mem_row_major);
    __syncthreads();
#pragma unroll
    for (int t = 0; t < 8; ++t) {
        int i = tid + t * 256;
        int row = i >> 4, c4 = i & 15;
        float4 v = *(float4*)(Cs + row * 72 + c4 * 4);
        int n = n0 + c4 * 4;
        if (MODE == 1) {
            v.x += bias[n];     v.y += bias[n + 1];  v.z += bias[n + 2];  v.w += bias[n + 3];
            v.x = v.x > 0.f ? v.x : 0.01f * v.x;
            v.y = v.y > 0.f ? v.y : 0.01f * v.y;
            v.z = v.z > 0.f ? v.z : 0.01f * v.z;
            v.w = v.w > 0.f ? v.w : 0.01f * v.w;
        } else if (MODE == 3) {
            float rs = rowscale[m0 + row];
            v.x += rs * bias[n];     v.y += rs * bias[n + 1];
            v.z += rs * bias[n + 2]; v.w += rs * bias[n + 3];
            v.x = v.x > 0.f ? v.x : expm1f(v.x);
            v.y = v.y > 0.f ? v.y : expm1f(v.y);
            v.z = v.z > 0.f ? v.z : expm1f(v.z);
            v.w = v.w > 0.f ? v.w : expm1f(v.w);
        }
        *(float4*)(C + (size_t)(m0 + row) * N + n) = v;
    }
}

// ---------------- block reductions ----------------
__device__ __forceinline__ float blk_sum(float v, float* red, int j)
{
#pragma unroll
    for (int o = 16; o > 0; o >>= 1) v += __shfl_down_sync(0xffffffffu, v, o);
    if ((j & 31) == 0) red[j >> 5] = v;
    __syncthreads();
    v = red[0] + red[1] + red[2] + red[3];
    __syncthreads();
    return v;
}
__device__ __forceinline__ float blk_max(float v, float* red, int j)
{
#pragma unroll
    for (int o = 16; o > 0; o >>= 1) v = fmaxf(v, __shfl_down_sync(0xffffffffu, v, o));
    if ((j & 31) == 0) red[j >> 5] = v;
    __syncthreads();
    v = fmaxf(fmaxf(red[0], red[1]), fmaxf(red[2], red[3]));
    __syncthreads();
    return v;
}

// ---------------- padding kernels ----------------
__global__ void pad_atom_k(const float* __restrict__ atom, float* __restrict__ out)
{
    int r = blockIdx.x, t = threadIdx.x;             // 64 threads
    out[(size_t)r * 64 + t] = (t < FAD) ? atom[(size_t)r * FAD + t] : 0.f;
}
__global__ void pad_bond_k(const float* __restrict__ bond, float* __restrict__ out)
{
    int r = blockIdx.x, t = threadIdx.x;             // 32 threads
    out[(size_t)r * 32 + t] = (t < FBD) ? bond[(size_t)r * FBD + t] : 0.f;
}
__global__ void pad_w_k(const float* __restrict__ w, float* __restrict__ out,
                        int Ksrc, int off)
{
    int r = blockIdx.x, j = threadIdx.x;
    out[r * 128 + j] = (r < Ksrc) ? w[(off + r) * 128 + j] : 0.f;
}

// ---------------- fused d=0 attention (neighbor features built on the fly) -
__global__ void attn0_k(const float* __restrict__ h, const float* __restrict__ atomT,
                        const float* __restrict__ bondT, const int* __restrict__ adl,
                        const int* __restrict__ bdl, const float* __restrict__ nbias,
                        const float* __restrict__ aw, const float* __restrict__ ab,
                        float* __restrict__ wnbr, float* __restrict__ sumw)
{
    int bl = blockIdx.x, j = threadIdx.x;            // 128 threads
    int bbase = (bl >> 7) << 7;                      // b * LLEN
    __shared__ float red[4];
    const int base = bl * KNBR;
    float sc = blk_sum(h[(size_t)bl * DDIM + j] * aw[j], red, j);
    float aw2 = aw[DDIM + j];
    float ab0 = ab[0];
    float nb  = nbias[j];
    float v[KNBR], s[KNBR], msk[KNBR];
#pragma unroll
    for (int k = 0; k < KNBR; ++k) {
        int ai = adl[base + k], bi = bdl[base + k];
        float x = atomT[(size_t)(bbase + ai) * DDIM + j]
                + bondT[(size_t)(bbase + bi) * DDIM + j] + nb;
        v[k] = x > 0.f ? x : 0.01f * x;
        msk[k] = (ai == LLEN - 1) ? 0.f : 1.f;
    }
#pragma unroll
    for (int k = 0; k < KNBR; ++k) {
        float d = blk_sum(v[k] * aw2, red, j);
        float sco = sc + d + ab0;
        sco = sco > 0.f ? sco : 0.01f * sco;
        if (msk[k] == 0.f) sco += NEGV;
        s[k] = sco;
    }
    float mx = -1e30f;
#pragma unroll
    for (int k = 0; k < KNBR; ++k) mx = fmaxf(mx, s[k]);
    float ss = 0.f;
#pragma unroll
    for (int k = 0; k < KNBR; ++k) { s[k] = expf(s[k] - mx); ss += s[k]; }
    float acc = 0.f, sw = 0.f;
#pragma unroll
    for (int k = 0; k < KNBR; ++k) {
        float w = s[k] / ss * msk[k];
        acc = fmaf(w, v[k], acc);
        sw += w;
    }
    wnbr[(size_t)bl * DDIM + j] = acc;
    if (j == 0) sumw[bl] = sw;
}

// ---------------- two dots in one pass over act ----------------
__global__ void dot2_k(const float* __restrict__ X, const float* __restrict__ w1,
                       const float* __restrict__ w2, float* __restrict__ o1,
                       float* __restrict__ o2)
{
    int row = blockIdx.x, j = threadIdx.x;
    __shared__ float red[4];
    float x = X[(size_t)row * DDIM + j];
    float a = blk_sum(x * w1[j], red, j);
    float b = blk_sum(x * w2[j], red, j);
    if (j == 0) { o1[row] = a; o2[row] = b; }
}
__global__ void dot128_k(const float* __restrict__ X, const float* __restrict__ v,
                         float* __restrict__ out)
{
    int row = blockIdx.x, j = threadIdx.x;
    __shared__ float red[4];
    float p = blk_sum(X[(size_t)row * DDIM + j] * v[j], red, j);
    if (j == 0) out[row] = p;
}

// ---------------- d>=1 attention (P raw: bias folded via sumw) -------------
__global__ void attn_k(const float* __restrict__ sc, const float* __restrict__ sn,
                       const float* __restrict__ P, const int* __restrict__ adl,
                       const float* __restrict__ abp, const float* __restrict__ tb,
                       float* __restrict__ ctx)
{
    int bl = blockIdx.x;
    int b  = bl >> 7;
    int j  = threadIdx.x;
    __shared__ float ws[KNBR];
    __shared__ float swsh;
    __shared__ int   rowidx[KNBR];
    if (j == 0) {
        float ab = abp[0];
        float s[KNBR], msk[KNBR];
        float mx = -1e30f;
#pragma unroll
        for (int k = 0; k < KNBR; ++k) {
            int id = adl[bl * KNBR + k];
            int src = b * LLEN + id;
            rowidx[k] = src;
            float sco = sc[bl] + sn[src] + ab;
            sco = sco > 0.f ? sco : 0.01f * sco;
            bool pad = (id == LLEN - 1);
            if (pad) sco += NEGV;
            msk[k] = pad ? 0.f : 1.f;
            s[k] = sco;
            mx = fmaxf(mx, sco);
        }
        float sum = 0.f;
#pragma unroll
        for (int k = 0; k < KNBR; ++k) { s[k] = expf(s[k] - mx); sum += s[k]; }
        float sw = 0.f;
#pragma unroll
        for (int k = 0; k < KNBR; ++k) { ws[k] = s[k] / sum * msk[k]; sw += ws[k]; }
        swsh = sw;
    }
    __syncthreads();
    float c = 0.f;
#pragma unroll
    for (int k = 0; k < KNBR; ++k)
        c = fmaf(ws[k], P[(size_t)rowidx[k] * DDIM + j], c);
    c += swsh * tb[j];
    c = c > 0.f ? c : expm1f(c);
    ctx[(size_t)bl * DDIM + j] = c;
}

// ---------------- GRU gate fusion (biases added here) ----------------
__global__ void gru_gate_k(const float* __restrict__ gi, const float* __restrict__ gh,
                           const float* __restrict__ bih, const float* __restrict__ bhh,
                           float* __restrict__ h, float* __restrict__ act, int M)
{
    int idx = blockIdx.x * blockDim.x + threadIdx.x;
    if (idx >= M * DDIM) return;
    int m = idx >> 7, j = idx & 127;
    size_t base = (size_t)m * 384;
    float ir = gi[base + j] + bih[j];
    float iz = gi[base + 128 + j] + bih[128 + j];
    float in = gi[base + 256 + j] + bih[256 + j];
    float hr = gh[base + j] + bhh[j];
    float hz = gh[base + 128 + j] + bhh[128 + j];
    float hn = gh[base + 256 + j] + bhh[256 + j];
    float r = 1.f / (1.f + expf(-(ir + hr)));
    float z = 1.f / (1.f + expf(-(iz + hz)));
    float n = tanhf(in + r * hn);
    float hv = h[idx];
    float hnew = (1.f - z) * n + z * hv;
    h[idx] = hnew;
    act[idx] = hnew > 0.f ? hnew : 0.f;
}

// ---------------- masked sum over atoms ----------------
__global__ void molsum_k(const float* __restrict__ act, const float* __restrict__ mask,
                         float* __restrict__ molf)
{
    int b = blockIdx.x, j = threadIdx.x;
    float s = 0.f;
    for (int l = 0; l < LLEN; ++l)
        s = fmaf(act[((size_t)b * LLEN + l) * DDIM + j], mask[b * LLEN + l], s);
    molf[b * DDIM + j] = s;
}

// ---------------- per-molecule mol-attention + GRU (T steps) ---------------
__global__ void mol_k(const float* __restrict__ molf_in, const float* __restrict__ mask,
                      const float* __restrict__ snm, const float* __restrict__ Pm,
                      const float* __restrict__ maw, const float* __restrict__ mab,
                      const float* __restrict__ matt_b,
                      const float* __restrict__ wih, const float* __restrict__ whh,
                      const float* __restrict__ bih, const float* __restrict__ bhh,
                      const float* __restrict__ outw, const float* __restrict__ outb,
                      float* __restrict__ molf_out, float* __restrict__ pred)
{
    int b = blockIdx.x;
    int j = threadIdx.x;                     // 128: feature index AND atom index
    __shared__ float smolf[DDIM];
    __shared__ float w[LLEN];
    __shared__ float sctx[DDIM];
    __shared__ float red[4];
    smolf[j] = molf_in[b * DDIM + j];
    float mymask = mask[b * LLEN + j];
    float mysnm  = snm[b * LLEN + j];
    float mabv   = mab[0];
    float mybias = matt_b[j];

    for (int t = 0; t < NTS; ++t) {
        __syncthreads();
        float amj = fmaxf(smolf[j], 0.f);
        float scv = blk_sum(amj * maw[j], red, j);
        float sco = scv + mysnm + mabv;
        sco = sco > 0.f ? sco : 0.01f * sco;
        if (mymask == 0.f) sco += NEGV;
        float mx = blk_max(sco, red, j);
        float ev = expf(sco - mx);
        float ss = blk_sum(ev, red, j);
        float wj = ev / ss * mymask;
        w[j] = wj;
        float sumw = blk_sum(wj, red, j);
        __syncthreads();
        float c = 0.f;
#pragma unroll 4
        for (int l = 0; l < LLEN; ++l)
            c = fmaf(w[l], Pm[((size_t)b * LLEN + l) * DDIM + j], c);
        c += sumw * mybias;
        c = c > 0.f ? c : expm1f(c);
        sctx[j] = c;
        __syncthreads();
        float gi0 = bih[j], gi1 = bih[DDIM + j], gi2 = bih[2 * DDIM + j];
        float gh0 = bhh[j], gh1 = bhh[DDIM + j], gh2 = bhh[2 * DDIM + j];
        const float* wi0 = wih + (size_t)j * DDIM;
        const float* wi1 = wih + (size_t)(DDIM + j) * DDIM;
        const float* wi2 = wih + (size_t)(2 * DDIM + j) * DDIM;
        const float* wh0 = whh + (size_t)j * DDIM;
        const float* wh1 = whh + (size_t)(DDIM + j) * DDIM;
        const float* wh2 = whh + (size_t)(2 * DDIM + j) * DDIM;
#pragma unroll 4
        for (int k = 0; k < DDIM; ++k) {
            float ck = sctx[k], hk = smolf[k];
            gi0 = fmaf(ck, wi0[k], gi0);
            gi1 = fmaf(ck, wi1[k], gi1);
            gi2 = fmaf(ck, wi2[k], gi2);
            gh0 = fmaf(hk, wh0[k], gh0);
            gh1 = fmaf(hk, wh1[k], gh1);
            gh2 = fmaf(hk, wh2[k], gh2);
        }
        float r = 1.f / (1.f + expf(-(gi0 + gh0)));
        float z = 1.f / (1.f + expf(-(gi1 + gh1)));
        float n = tanhf(gi2 + r * gh2);
        float hnew = (1.f - z) * n + z * smolf[j];
        __syncthreads();
        smolf[j] = hnew;
    }
    __syncthreads();
    molf_out[b * DDIM + j] = smolf[j];
    float tot = blk_sum(smolf[j] * outw[j], red, j);
    if (j == 0) pred[b] = tot + outb[0];
}

__global__ void copy_k(const float* __restrict__ src, float* __restrict__ dst, int n)
{
    int i = blockIdx.x * blockDim.x + threadIdx.x;
    if (i < n) dst[i] = src[i];
}

// ---------------- launcher ----------------
extern "C" void kernel_launch(void* const* d_in, const int* in_sizes, int n_in,
                              void* d_out, int out_size)
{
    const float* atom_list    = (const float*)d_in[0];
    const float* bond_list    = (const float*)d_in[1];
    const float* atom_mask    = (const float*)d_in[2];
    const float* atom_fc_w    = (const float*)d_in[3];
    const float* atom_fc_b    = (const float*)d_in[4];
    const float* nbr_fc_w     = (const float*)d_in[5];
    const float* nbr_fc_b     = (const float*)d_in[6];
    const float* align_w      = (const float*)d_in[7];   // [R, 2D]
    const float* align_b      = (const float*)d_in[8];   // [R]
    const float* attend_w     = (const float*)d_in[9];   // [R, D, D]
    const float* attend_b     = (const float*)d_in[10];  // [R, D]
    const float* gru_wih      = (const float*)d_in[11];  // [R, 3D, D]
    const float* gru_whh      = (const float*)d_in[12];
    const float* gru_bih      = (const float*)d_in[13];  // [R, 3D]
    const float* gru_bhh      = (const float*)d_in[14];
    const float* mol_align_w  = (const float*)d_in[15];  // [2D]
    const float* mol_align_b  = (const float*)d_in[16];  // [1]
    const float* mol_attend_w = (const float*)d_in[17];  // [D, D]
    const float* mol_attend_b = (const float*)d_in[18];  // [D]
    const float* mol_gru_wih  = (const float*)d_in[19];  // [3D, D]
    const float* mol_gru_whh  = (const float*)d_in[20];
    const float* mol_gru_bih  = (const float*)d_in[21];
    const float* mol_gru_bhh  = (const float*)d_in[22];
    const float* out_w        = (const float*)d_in[23];  // [D]
    const float* out_b        = (const float*)d_in[24];  // [1]
    const int*   adl          = (const int*)d_in[25];    // [B, L, K]
    const int*   bdl          = (const int*)d_in[26];

    float *p_h, *p_act, *p_ctx, *p_P, *p_atomT, *p_bondT, *p_A64, *p_B32,
          *p_gi, *p_gh, *p_sc, *p_sn, *p_sumw, *p_Wa, *p_Wt, *p_Wb,
          *p_molf, *p_pred;
    cudaGetSymbolAddress((void**)&p_h,     g_h);
    cudaGetSymbolAddress((void**)&p_act,   g_act);
    cudaGetSymbolAddress((void**)&p_ctx,   g_ctx);
    cudaGetSymbolAddress((void**)&p_P,     g_P);
    cudaGetSymbolAddress((void**)&p_atomT, g_atomT);
    cudaGetSymbolAddress((void**)&p_bondT, g_bondT);
    cudaGetSymbolAddress((void**)&p_A64,   g_A64);
    cudaGetSymbolAddress((void**)&p_B32,   g_B32);
    cudaGetSymbolAddress((void**)&p_gi,    g_gi);
    cudaGetSymbolAddress((void**)&p_gh,    g_gh);
    cudaGetSymbolAddress((void**)&p_sc,    g_sc);
    cudaGetSymbolAddress((void**)&p_sn,    g_sn);
    cudaGetSymbolAddress((void**)&p_sumw,  g_sumw);
    cudaGetSymbolAddress((void**)&p_Wa,    g_Wa);
    cudaGetSymbolAddress((void**)&p_Wt,    g_Wt);
    cudaGetSymbolAddress((void**)&p_Wb,    g_Wb);
    cudaGetSymbolAddress((void**)&p_molf,  g_molf);
    cudaGetSymbolAddress((void**)&p_pred,  g_pred);

    float* out = (float*)d_out;
    const int gA = M_ATOM / 128;  // 256

    // ---- pad inputs / weights ----
    pad_atom_k<<<M_ATOM, 64>>>(atom_list, p_A64);
    pad_bond_k<<<M_ATOM, 32>>>(bond_list, p_B32);
    pad_w_k<<<64, 128>>>(atom_fc_w, p_Wa, FAD, 0);        // atom fc weight
    pad_w_k<<<64, 128>>>(nbr_fc_w,  p_Wt, FAD, 0);        // nbr fc: atom part
    pad_w_k<<<32, 128>>>(nbr_fc_w,  p_Wb, FBD, FAD);      // nbr fc: bond part

    // atom_feature -> h ; factored nbr transforms (raw)
    gemm_bf16x3_k<0,1><<<dim3(gA, 2), 256>>>(p_A64, p_Wa, atom_fc_b, nullptr, p_h,     M_ATOM, 64, DDIM);
    gemm_bf16x3_k<0,0><<<dim3(gA, 2), 256>>>(p_A64, p_Wt, nullptr,   nullptr, p_atomT, M_ATOM, 64, DDIM);
    gemm_bf16x3_k<0,0><<<dim3(gA, 2), 256>>>(p_B32, p_Wb, nullptr,   nullptr, p_bondT, M_ATOM, 32, DDIM);

    // ---- radius 0: fused attention, then transform the weighted sum ----
    attn0_k<<<M_ATOM, 128>>>(p_h, p_atomT, p_bondT, adl, bdl, nbr_fc_b,
                             align_w, align_b, p_P, p_sumw);
    gemm_bf16x3_k<0,3><<<dim3(gA, 2), 256>>>(p_P, attend_w, attend_b, p_sumw, p_ctx, M_ATOM, DDIM, DDIM);
    gemm_bf16x3_k<1,0><<<dim3(gA, 6), 256>>>(p_ctx, gru_wih, nullptr, nullptr, p_gi, M_ATOM, DDIM, 384);
    gemm_bf16x3_k<1,0><<<dim3(gA, 6), 256>>>(p_h,   gru_whh, nullptr, nullptr, p_gh, M_ATOM, DDIM, 384);
    gru_gate_k<<<(M_ATOM * DDIM + 255) / 256, 256>>>(p_gi, p_gh, gru_bih, gru_bhh, p_h, p_act, M_ATOM);

    // ---- radii 1..R-1 ----
    for (int d = 1; d < NRAD; ++d) {
        dot2_k<<<M_ATOM, 128>>>(p_act, align_w + d * 2 * DDIM, align_w + d * 2 * DDIM + DDIM, p_sc, p_sn);
        gemm_bf16x3_k<0,0><<<dim3(gA, 2), 256>>>(p_act, attend_w + (size_t)d * DDIM * DDIM,
                                                 nullptr, nullptr, p_P, M_ATOM, DDIM, DDIM);
        attn_k<<<M_ATOM, 128>>>(p_sc, p_sn, p_P, adl, align_b + d, attend_b + d * DDIM, p_ctx);
        gemm_bf16x3_k<1,0><<<dim3(gA, 6), 256>>>(p_ctx, gru_wih + (size_t)d * 384 * DDIM,
                                                 nullptr, nullptr, p_gi, M_ATOM, DDIM, 384);
        gemm_bf16x3_k<1,0><<<dim3(gA, 6), 256>>>(p_h, gru_whh + (size_t)d * 384 * DDIM,
                                                 nullptr, nullptr, p_gh, M_ATOM, DDIM, 384);
        gru_gate_k<<<(M_ATOM * DDIM + 255) / 256, 256>>>(p_gi, p_gh, gru_bih + d * 384,
                                                         gru_bhh + d * 384, p_h, p_act, M_ATOM);
    }

    // ---- molecule phase ----
    molsum_k<<<BBATCH, 128>>>(p_act, atom_mask, p_molf);
    gemm_bf16x3_k<0,0><<<dim3(gA, 2), 256>>>(p_act, mol_attend_w, nullptr, nullptr, p_P, M_ATOM, DDIM, DDIM);
    dot128_k<<<M_ATOM, 128>>>(p_act, mol_align_w + DDIM, p_sn);
    mol_k<<<BBATCH, 128>>>(p_molf, atom_mask, p_sn, p_P, mol_align_w, mol_align_b, mol_attend_b,
                           mol_gru_wih, mol_gru_whh, mol_gru_bih, mol_gru_bhh,
                           out_w, out_b, p_molf, p_pred);

    // ---- outputs: (h, mol_prediction) flattened ----
    const int HN = M_ATOM * DDIM;
    if (out_size >= HN + BBATCH) {
        copy_k<<<(HN + 255) / 256, 256>>>(p_h, out, HN);
        copy_k<<<1, 256>>>(p_pred, out + HN, BBATCH);
    } else if (out_size == BBATCH) {
        copy_k<<<1, 256>>>(p_pred, out, BBATCH);
    } else {
        int n = out_size < HN ? out_size : HN;
        copy_k<<<(n + 255) / 256, 256>>>(p_h, out, n);
    }
    (void)in_sizes; (void)n_in;
}